// round 4
// baseline (speedup 1.0000x reference)
#include <cuda_runtime.h>

#define N0 48000
#define N1MAX 32000
#define EPSV 1e-4f

// ---------------- scratch (device globals; no allocation) ----------------
__device__ float g_f0a[(N0 + 1) * 32];
__device__ float g_f0b[(N0 + 1) * 32];
__device__ float g_f0c[(N0 + 1) * 32];
__device__ float g_cat[(N0 + 1) * 64];
__device__ float g_f1a[(N1MAX + 1) * 64];
__device__ float g_f1b[(N1MAX + 1) * 64];
__device__ float g_f1c[(N1MAX + 1) * 64];
__device__ int g_nbr0[(N0 + 1) * 27];
__device__ int g_nbr1[(N1MAX + 1) * 27];
__device__ int g_nbrD[(N1MAX + 1) * 8];
__device__ int g_parent[N0 + 1];
__device__ int g_kid[N0 + 1];

// ---------------- f32x2 helpers ----------------
union F2U { float2 f2; unsigned long long u; };

__device__ __forceinline__ void ffma2(unsigned long long& acc, unsigned long long a,
                                      unsigned long long b) {
    asm("fma.rn.f32x2 %0, %1, %2, %0;" : "+l"(acc) : "l"(a), "l"(b));
}

// ---------------- small utility kernels ----------------
__global__ void fill_i32(int* p, int count, int val, const int* vptr) {
    int t = blockIdx.x * blockDim.x + threadIdx.x;
    if (t >= count) return;
    p[t] = vptr ? *vptr : val;
}

__global__ void scatter_pairs(const int* __restrict__ pin, const int* __restrict__ pout,
                              int total, int P, int K, int* __restrict__ nbr) {
    int t = blockIdx.x * blockDim.x + threadIdx.x;
    if (t >= total) return;
    int k = t / P;
    nbr[pout[t] * K + k] = pin[t];
}

__global__ void scatter_parent(const int* __restrict__ din, const int* __restrict__ dout,
                               int total, int P, int n0,
                               int* __restrict__ parent, int* __restrict__ kid) {
    int t = blockIdx.x * blockDim.x + threadIdx.x;
    if (t >= total) return;
    int k = t / P;
    int i = din[t];
    if (i < n0) { parent[i] = dout[t]; kid[i] = k; }
}

template <int C>
__global__ void bnrelu_k(const float* __restrict__ x, const float* __restrict__ bn,
                         float* __restrict__ y, int n_host, const int* __restrict__ n_dev,
                         int total) {
    int t = blockIdx.x * blockDim.x + threadIdx.x;
    if (t >= total) return;
    int n = n_dev ? *n_dev : n_host;
    int r = t / C, c = t % C;
    float v = 0.f;
    if (r < n) {
        float g = bn[c], be = bn[C + c], m = bn[2 * C + c], va = bn[3 * C + c];
        v = fmaxf((x[t] - m) * (g * rsqrtf(va + EPSV)) + be, 0.f);
    }
    y[t] = v;
}

// ---------------- gather implicit-GEMM sparse conv ----------------
// out[r,:] = sum_k bnrelu(x[nbr[r][k],:]) @ W[k]  (+ res[r,:])
// dynamic smem: Xs[CIN*68] | WsD[CIN*2*COUT] | idxAll[64*K] | sc[CIN] | bi[CIN]
template <int CIN, int COUT>
__global__ void conv_gather(const float* __restrict__ x, const float* __restrict__ bn,
                            const float* __restrict__ W,
                            const int* __restrict__ nbr, int K,
                            const float* __restrict__ res, float* __restrict__ out,
                            int nout_h, const int* __restrict__ nout_d,
                            int nin_h, const int* __restrict__ nin_d) {
    constexpr int BR = 64, P = 68;          // 68*4 = 272 B, 16B-aligned rows
    constexpr int TCOL = COUT / 4;
    constexpr int NT = 16 * TCOL;
    extern __shared__ float smem[];
    float* Xs  = smem;                       // CIN*P
    float* WsD = Xs + CIN * P;               // CIN*2*COUT (dup-expanded)
    int*   idxAll = (int*)(WsD + CIN * 2 * COUT);  // BR*K
    float* sc = (float*)(idxAll + BR * K);   // CIN
    float* bi = sc + CIN;                    // CIN

    int n = nout_d ? *nout_d : nout_h;
    int nin = nin_d ? *nin_d : nin_h;
    int row0 = blockIdx.x * BR;
    if (row0 >= n) return;
    int tid = threadIdx.x;
    int tc = tid % TCOL, tr = tid / TCOL;

    // preload: bn coefficients + whole idx tile (coalesced)
    if (tid < CIN) {
        float g = bn[tid], be = bn[CIN + tid], m = bn[2 * CIN + tid], va = bn[3 * CIN + tid];
        float s = g * rsqrtf(va + EPSV);
        sc[tid] = s;
        bi[tid] = be - m * s;
    }
    for (int e = tid; e < BR * K; e += NT)
        idxAll[e] = (row0 + e / K < n) ? nbr[(size_t)row0 * K + e] : nin;

    unsigned long long acc[2][4];
#pragma unroll
    for (int a = 0; a < 2; a++)
#pragma unroll
        for (int j = 0; j < 4; j++) acc[a][j] = 0ull;

    for (int k = 0; k < K; ++k) {
        __syncthreads();  // k=0: preload done; k>0: compute(k-1) done, Xs/WsD free
        // gather + bnrelu, store transposed
#pragma unroll
        for (int e = tid; e < BR * (CIN / 4); e += NT) {
            int r = e / (CIN / 4), c4 = e % (CIN / 4);
            int idx = idxAll[r * K + k];
            float4 v = make_float4(0.f, 0.f, 0.f, 0.f);
            if (idx < nin) {
                v = *reinterpret_cast<const float4*>(x + (size_t)idx * CIN + c4 * 4);
                int c = c4 * 4;
                v.x = fmaxf(v.x * sc[c + 0] + bi[c + 0], 0.f);
                v.y = fmaxf(v.y * sc[c + 1] + bi[c + 1], 0.f);
                v.z = fmaxf(v.z * sc[c + 2] + bi[c + 2], 0.f);
                v.w = fmaxf(v.w * sc[c + 3] + bi[c + 3], 0.f);
            }
            Xs[(c4 * 4 + 0) * P + r] = v.x;
            Xs[(c4 * 4 + 1) * P + r] = v.y;
            Xs[(c4 * 4 + 2) * P + r] = v.z;
            Xs[(c4 * 4 + 3) * P + r] = v.w;
        }
        // weights, dup-expanded: WsD[ci][2j] = WsD[ci][2j+1] = W[k][ci][j]
#pragma unroll
        for (int e = tid; e < CIN * COUT / 4; e += NT) {
            float4 w = *reinterpret_cast<const float4*>(W + (size_t)k * CIN * COUT + e * 4);
            float4 a = make_float4(w.x, w.x, w.y, w.y);
            float4 b = make_float4(w.z, w.z, w.w, w.w);
            reinterpret_cast<float4*>(WsD)[e * 2 + 0] = a;
            reinterpret_cast<float4*>(WsD)[e * 2 + 1] = b;
        }
        __syncthreads();
#pragma unroll
        for (int ci = 0; ci < CIN; ++ci) {
            ulonglong2 xp = *reinterpret_cast<const ulonglong2*>(&Xs[ci * P + tr * 4]);
            ulonglong2 wA = *reinterpret_cast<const ulonglong2*>(&WsD[ci * 2 * COUT + tc * 8]);
            ulonglong2 wB = *reinterpret_cast<const ulonglong2*>(&WsD[ci * 2 * COUT + tc * 8 + 4]);
            ffma2(acc[0][0], xp.x, wA.x);
            ffma2(acc[1][0], xp.y, wA.x);
            ffma2(acc[0][1], xp.x, wA.y);
            ffma2(acc[1][1], xp.y, wA.y);
            ffma2(acc[0][2], xp.x, wB.x);
            ffma2(acc[1][2], xp.y, wB.x);
            ffma2(acc[0][3], xp.x, wB.y);
            ffma2(acc[1][3], xp.y, wB.y);
        }
    }
    // epilogue
#pragma unroll
    for (int a = 0; a < 2; a++) {
#pragma unroll
        for (int u = 0; u < 2; u++) {
            int r = row0 + tr * 4 + a * 2 + u;
            if (r < n) {
#pragma unroll
                for (int j = 0; j < 4; j++) {
                    F2U t;
                    t.u = acc[a][j];
                    float v = u ? t.f2.y : t.f2.x;
                    int c = tc * 4 + j;
                    if (res) v += res[(size_t)r * COUT + c];
                    out[(size_t)r * COUT + c] = v;
                }
            }
        }
    }
}

// cat[i, 0:32] = identity[i,:]; cat[i, 32:64] = x1b[parent[i],:] @ up_W[kid[i]]
__global__ void up_concat(const float* __restrict__ idt, const float* __restrict__ x1,
                          const float* __restrict__ upW,
                          const int* __restrict__ parent, const int* __restrict__ kid,
                          float* __restrict__ cat, int n0) {
    int t = blockIdx.x * blockDim.x + threadIdx.x;
    if (t >= n0 * 64) return;
    int i = t / 64, c = t % 64;
    if (c < 32) {
        cat[t] = idt[(size_t)i * 32 + c];
    } else {
        const float* xr = x1 + (size_t)parent[i] * 64;
        const float* w = upW + (size_t)kid[i] * 64 * 32 + (c - 32);
        float a = 0.f;
#pragma unroll
        for (int ci = 0; ci < 64; ++ci) a += xr[ci] * w[ci * 32];
        cat[t] = a;
    }
}

// out[i,c] = h[i,c] + cat[i,:] @ Wsc[:,c]
__global__ void wsc_add(const float* __restrict__ h, const float* __restrict__ cat,
                        const float* __restrict__ Wsc, float* __restrict__ out, int n0) {
    int t = blockIdx.x * blockDim.x + threadIdx.x;
    if (t >= n0 * 32) return;
    int i = t / 32, c = t % 32;
    float a = h[t];
    const float* xr = cat + (size_t)i * 64;
#pragma unroll
    for (int ci = 0; ci < 64; ++ci) a += xr[ci] * Wsc[ci * 32 + c];
    out[t] = a;
}

// ---------------- host-side orchestration ----------------
static inline int ceil_div(int a, int b) { return (a + b - 1) / b; }
static inline int conv_smem(int cin, int cout, int K) {
    return 4 * (cin * 68 + cin * 2 * cout + 64 * K + 2 * cin);
}

extern "C" void kernel_launch(void* const* d_in, const int* in_sizes, int n_in,
                              void* d_out, int out_size) {
    const float* feats     = (const float*)d_in[0];
    const float* res0_W    = (const float*)d_in[1];
    const float* res0_bn   = (const float*)d_in[2];
    const float* down_bn   = (const float*)d_in[3];
    const float* down_W    = (const float*)d_in[4];
    const float* res1_W    = (const float*)d_in[5];
    const float* res1_bn   = (const float*)d_in[6];
    const float* up_bn     = (const float*)d_in[7];
    const float* up_W      = (const float*)d_in[8];
    const float* tail0_bn1 = (const float*)d_in[9];
    const float* tail0_W1  = (const float*)d_in[10];
    const float* tail0_bn2 = (const float*)d_in[11];
    const float* tail0_W2  = (const float*)d_in[12];
    const float* tail0_Wsc = (const float*)d_in[13];
    const float* tail1_W   = (const float*)d_in[14];
    const float* tail1_bn  = (const float*)d_in[15];
    const int* subm0_in    = (const int*)d_in[16];
    const int* subm0_out   = (const int*)d_in[17];
    const int* subm1_in    = (const int*)d_in[18];
    const int* subm1_out   = (const int*)d_in[19];
    const int* down_in     = (const int*)d_in[20];
    const int* down_out    = (const int*)d_in[21];
    const int* n1p         = (const int*)d_in[22];

    const int n0 = in_sizes[0] / 32;
    const int P0 = in_sizes[16] / 27;
    const int P1 = in_sizes[18] / 27;
    const int PD = in_sizes[20] / 8;

    float *f0a, *f0b, *f0c, *cat, *f1a, *f1b, *f1c;
    int *nbr0, *nbr1, *nbrD, *parent, *kid;
    cudaGetSymbolAddress((void**)&f0a, g_f0a);
    cudaGetSymbolAddress((void**)&f0b, g_f0b);
    cudaGetSymbolAddress((void**)&f0c, g_f0c);
    cudaGetSymbolAddress((void**)&cat, g_cat);
    cudaGetSymbolAddress((void**)&f1a, g_f1a);
    cudaGetSymbolAddress((void**)&f1b, g_f1b);
    cudaGetSymbolAddress((void**)&f1c, g_f1c);
    cudaGetSymbolAddress((void**)&nbr0, g_nbr0);
    cudaGetSymbolAddress((void**)&nbr1, g_nbr1);
    cudaGetSymbolAddress((void**)&nbrD, g_nbrD);
    cudaGetSymbolAddress((void**)&parent, g_parent);
    cudaGetSymbolAddress((void**)&kid, g_kid);

    // raise dynamic smem limit for the big C64 instantiation (57.8 KB)
    cudaFuncSetAttribute(conv_gather<64, 64>, cudaFuncAttributeMaxDynamicSharedMemorySize,
                         conv_smem(64, 64, 27));

    const int TB = 256;
    const int G0 = ceil_div(n0, 64);
    const int G1 = ceil_div(N1MAX, 64);
    const int E164 = (N1MAX + 1) * 64;
    const int S3232 = conv_smem(32, 32, 27);
    const int S3264 = conv_smem(32, 64, 8);
    const int S6464 = conv_smem(64, 64, 27);
    const int S6432 = conv_smem(64, 32, 27);

    // ---- level-0 rulebook, then res0 convs (so ncu -s 5 lands on a conv) ----
    fill_i32<<<ceil_div((N0 + 1) * 27, TB), TB>>>(nbr0, (N0 + 1) * 27, n0, nullptr);         // 1
    scatter_pairs<<<ceil_div(27 * P0, TB), TB>>>(subm0_in, subm0_out, 27 * P0, P0, 27, nbr0); // 2

    const float* x = feats;
    for (int rep = 0; rep < 2; ++rep) {                                                       // 3-6
        conv_gather<32, 32><<<G0, 128, S3232>>>(x, res0_bn + (rep * 2 + 0) * 128,
                                                res0_W + (size_t)(rep * 2 + 0) * 27 * 1024,
                                                nbr0, 27, nullptr, f0c, n0, nullptr, n0, nullptr);
        conv_gather<32, 32><<<G0, 128, S3232>>>(f0c, res0_bn + (rep * 2 + 1) * 128,
                                                res0_W + (size_t)(rep * 2 + 1) * 27 * 1024,
                                                nbr0, 27, x, f0a, n0, nullptr, n0, nullptr);
        x = f0a;
    }
    // f0a = identity

    // ---- remaining rulebooks ----
    fill_i32<<<ceil_div((N1MAX + 1) * 27, TB), TB>>>(nbr1, (N1MAX + 1) * 27, 0, n1p);
    scatter_pairs<<<ceil_div(27 * P1, TB), TB>>>(subm1_in, subm1_out, 27 * P1, P1, 27, nbr1);
    fill_i32<<<ceil_div((N1MAX + 1) * 8, TB), TB>>>(nbrD, (N1MAX + 1) * 8, n0, nullptr);
    scatter_pairs<<<ceil_div(8 * PD, TB), TB>>>(down_in, down_out, 8 * PD, PD, 8, nbrD);
    fill_i32<<<ceil_div(N0 + 1, TB), TB>>>(parent, N0 + 1, 0, n1p);
    fill_i32<<<ceil_div(N0 + 1, TB), TB>>>(kid, N0 + 1, 0, nullptr);
    scatter_parent<<<ceil_div(8 * PD, TB), TB>>>(down_in, down_out, 8 * PD, PD, n0, parent, kid);

    // ---- down conv (n_out = n1 dev, n_in = n0) ----
    conv_gather<32, 64><<<G1, 256, S3264>>>(f0a, down_bn, down_W, nbrD, 8, nullptr, f1a,
                                            0, n1p, n0, nullptr);

    // ---- res1 blocks (level 1, C=64) ----
    for (int rep = 0; rep < 2; ++rep) {
        conv_gather<64, 64><<<G1, 256, S6464>>>(f1a, res1_bn + (rep * 2 + 0) * 256,
                                                res1_W + (size_t)(rep * 2 + 0) * 27 * 4096,
                                                nbr1, 27, nullptr, f1c, 0, n1p, 0, n1p);
        conv_gather<64, 64><<<G1, 256, S6464>>>(f1c, res1_bn + (rep * 2 + 1) * 256,
                                                res1_W + (size_t)(rep * 2 + 1) * 27 * 4096,
                                                nbr1, 27, f1a, f1a, 0, n1p, 0, n1p);
    }

    // ---- up conv + concat ----
    bnrelu_k<64><<<ceil_div(E164, TB), TB>>>(f1a, up_bn, f1b, 0, n1p, E164);
    up_concat<<<ceil_div(n0 * 64, TB), TB>>>(f0a, f1b, up_W, parent, kid, cat, n0);

    // ---- tail0 ----
    conv_gather<64, 32><<<G0, 128, S6432>>>(cat, tail0_bn1, tail0_W1, nbr0, 27, nullptr, f0b,
                                            n0, nullptr, n0, nullptr);
    conv_gather<32, 32><<<G0, 128, S3232>>>(f0b, tail0_bn2, tail0_W2, nbr0, 27, nullptr, f0c,
                                            n0, nullptr, n0, nullptr);
    wsc_add<<<ceil_div(n0 * 32, TB), TB>>>(f0c, cat, tail0_Wsc, f0b, n0);

    // ---- tail1 res block -> d_out ----
    conv_gather<32, 32><<<G0, 128, S3232>>>(f0b, tail1_bn + 0, tail1_W, nbr0, 27, nullptr, f0a,
                                            n0, nullptr, n0, nullptr);
    conv_gather<32, 32><<<G0, 128, S3232>>>(f0a, tail1_bn + 128, tail1_W + 27 * 1024, nbr0, 27,
                                            f0b, (float*)d_out, n0, nullptr, n0, nullptr);
}

// round 5
// speedup vs baseline: 2.2619x; 2.2619x over previous
#include <cuda_runtime.h>

#define N0 48000
#define N1MAX 32000
#define EPSV 1e-4f

// ---------------- scratch (device globals; no allocation) ----------------
__device__ float g_f0a[(N0 + 1) * 32];
__device__ float g_f0b[(N0 + 1) * 32];
__device__ float g_f0c[(N0 + 1) * 32];
__device__ float g_cat[(N0 + 1) * 64];
__device__ float g_f1a[(N1MAX + 1) * 64];
__device__ float g_f1b[(N1MAX + 1) * 64];
__device__ float g_f1c[(N1MAX + 1) * 64];
__device__ int g_nbr0[(N0 + 1) * 27];
__device__ int g_nbr1[(N1MAX + 1) * 27];
__device__ int g_nbrD[(N1MAX + 1) * 8];
__device__ int g_parent[N0 + 1];
__device__ int g_kid[N0 + 1];

// ---------------- f32x2 helpers ----------------
union F2U { float2 f2; unsigned long long u; };

__device__ __forceinline__ unsigned long long dup2(float v) {
    unsigned long long r;
    asm("mov.b64 %0, {%1, %1};" : "=l"(r) : "f"(v));
    return r;
}
__device__ __forceinline__ void ffma2(unsigned long long& acc, unsigned long long a,
                                      unsigned long long b) {
    asm("fma.rn.f32x2 %0, %1, %2, %0;" : "+l"(acc) : "l"(a), "l"(b));
}

// ---------------- small utility kernels ----------------
__global__ void fill_i32(int* p, int count, int val, const int* vptr) {
    int t = blockIdx.x * blockDim.x + threadIdx.x;
    if (t >= count) return;
    p[t] = vptr ? *vptr : val;
}

__global__ void scatter_pairs(const int* __restrict__ pin, const int* __restrict__ pout,
                              int total, int P, int K, int* __restrict__ nbr) {
    int t = blockIdx.x * blockDim.x + threadIdx.x;
    if (t >= total) return;
    int k = t / P;
    nbr[pout[t] * K + k] = pin[t];
}

__global__ void scatter_parent(const int* __restrict__ din, const int* __restrict__ dout,
                               int total, int P, int n0,
                               int* __restrict__ parent, int* __restrict__ kid) {
    int t = blockIdx.x * blockDim.x + threadIdx.x;
    if (t >= total) return;
    int k = t / P;
    int i = din[t];
    if (i < n0) { parent[i] = dout[t]; kid[i] = k; }
}

template <int C>
__global__ void bnrelu_k(const float* __restrict__ x, const float* __restrict__ bn,
                         float* __restrict__ y, int n_host, const int* __restrict__ n_dev,
                         int total) {
    int t = blockIdx.x * blockDim.x + threadIdx.x;
    if (t >= total) return;
    int n = n_dev ? *n_dev : n_host;
    int r = t / C, c = t % C;
    float v = 0.f;
    if (r < n) {
        float g = bn[c], be = bn[C + c], m = bn[2 * C + c], va = bn[3 * C + c];
        v = fmaxf((x[t] - m) * (g * rsqrtf(va + EPSV)) + be, 0.f);
    }
    y[t] = v;
}

// ---------------- gather implicit-GEMM sparse conv ----------------
// out[r,:] = sum_k bnrelu(x[nbr[r][k],:]) @ W[k]  (+ res[r,:])
// Thread tile: 8 rows x 4 cols (4 row-pairs, packed f32x2 accumulators).
// Xs layout: pair-packed transposed Xs[ci][m] = {x_{2m}, x_{2m+1}}, odd pitch P2.
template <int CIN, int COUT, int BR>
__global__ void conv_gather(const float* __restrict__ x, const float* __restrict__ bn,
                            const float* __restrict__ W,
                            const int* __restrict__ nbr, int K,
                            const float* __restrict__ res, float* __restrict__ out,
                            int nout_h, const int* __restrict__ nout_d,
                            int nin_h, const int* __restrict__ nin_d) {
    constexpr int NPAIR = BR / 2;
    constexpr int P2 = NPAIR + 1;          // odd pitch (float2 units) -> spread STS banks
    constexpr int TCOL = COUT / 4;
    constexpr int GR = BR / 8;             // thread row-groups
    constexpr int NT = GR * TCOL;
    extern __shared__ float smem[];
    float2* Xs  = (float2*)smem;                   // CIN * P2 float2
    float*  Ws  = smem + CIN * P2 * 2;             // CIN * COUT
    int* idxAll = (int*)(Ws + CIN * COUT);         // BR * K
    float* sc   = (float*)(idxAll + BR * K);       // CIN
    float* bi   = sc + CIN;                        // CIN

    int n = nout_d ? *nout_d : nout_h;
    int nin = nin_d ? *nin_d : nin_h;
    int tid = threadIdx.x;
    int tc = tid % TCOL, tr = tid / TCOL;

    if (tid < CIN) {
        float g = bn[tid], be = bn[CIN + tid], m = bn[2 * CIN + tid], va = bn[3 * CIN + tid];
        float s = g * rsqrtf(va + EPSV);
        sc[tid] = s;
        bi[tid] = be - m * s;
    }

    for (int tile = blockIdx.x; tile * BR < n; tile += gridDim.x) {
        int row0 = tile * BR;
        __syncthreads();  // idxAll free (prev tile done); also orders sc/bi on first pass
        for (int e = tid; e < BR * K; e += NT)
            idxAll[e] = (row0 + e / K < n) ? nbr[(size_t)row0 * K + e] : nin;

        unsigned long long acc[4][4];
#pragma unroll
        for (int a = 0; a < 4; a++)
#pragma unroll
            for (int j = 0; j < 4; j++) acc[a][j] = 0ull;

        for (int k = 0; k < K; ++k) {
            __syncthreads();  // idxAll ready / prev compute done
            // gather + bnrelu two rows, store pair-packed transposed
            for (int e = tid; e < NPAIR * (CIN / 4); e += NT) {
                int m = e / (CIN / 4), c4 = e % (CIN / 4);
                int i0 = idxAll[(2 * m + 0) * K + k];
                int i1 = idxAll[(2 * m + 1) * K + k];
                float4 v0 = make_float4(0.f, 0.f, 0.f, 0.f);
                float4 v1 = make_float4(0.f, 0.f, 0.f, 0.f);
                int c = c4 * 4;
                if (i0 < nin) {
                    v0 = *reinterpret_cast<const float4*>(x + (size_t)i0 * CIN + c);
                    v0.x = fmaxf(fmaf(v0.x, sc[c + 0], bi[c + 0]), 0.f);
                    v0.y = fmaxf(fmaf(v0.y, sc[c + 1], bi[c + 1]), 0.f);
                    v0.z = fmaxf(fmaf(v0.z, sc[c + 2], bi[c + 2]), 0.f);
                    v0.w = fmaxf(fmaf(v0.w, sc[c + 3], bi[c + 3]), 0.f);
                }
                if (i1 < nin) {
                    v1 = *reinterpret_cast<const float4*>(x + (size_t)i1 * CIN + c);
                    v1.x = fmaxf(fmaf(v1.x, sc[c + 0], bi[c + 0]), 0.f);
                    v1.y = fmaxf(fmaf(v1.y, sc[c + 1], bi[c + 1]), 0.f);
                    v1.z = fmaxf(fmaf(v1.z, sc[c + 2], bi[c + 2]), 0.f);
                    v1.w = fmaxf(fmaf(v1.w, sc[c + 3], bi[c + 3]), 0.f);
                }
                Xs[(c + 0) * P2 + m] = make_float2(v0.x, v1.x);
                Xs[(c + 1) * P2 + m] = make_float2(v0.y, v1.y);
                Xs[(c + 2) * P2 + m] = make_float2(v0.z, v1.z);
                Xs[(c + 3) * P2 + m] = make_float2(v0.w, v1.w);
            }
            // weights (plain, no duplication)
            for (int e = tid; e < CIN * COUT / 4; e += NT)
                *reinterpret_cast<float4*>(Ws + e * 4) =
                    *reinterpret_cast<const float4*>(W + (size_t)k * CIN * COUT + e * 4);
            __syncthreads();
#pragma unroll
            for (int ci = 0; ci < CIN; ++ci) {
                F2U xp[4];
#pragma unroll
                for (int i = 0; i < 4; i++) xp[i].f2 = Xs[ci * P2 + tr * 4 + i];
                float4 w = *reinterpret_cast<const float4*>(&Ws[ci * COUT + tc * 4]);
                unsigned long long w0 = dup2(w.x), w1 = dup2(w.y), w2 = dup2(w.z), w3 = dup2(w.w);
#pragma unroll
                for (int i = 0; i < 4; i++) {
                    ffma2(acc[i][0], xp[i].u, w0);
                    ffma2(acc[i][1], xp[i].u, w1);
                    ffma2(acc[i][2], xp[i].u, w2);
                    ffma2(acc[i][3], xp[i].u, w3);
                }
            }
        }
        // epilogue: pair i -> rows row0 + (tr*4+i)*2 + {0,1}
#pragma unroll
        for (int i = 0; i < 4; i++) {
            int rb = row0 + (tr * 4 + i) * 2;
#pragma unroll
            for (int u = 0; u < 2; u++) {
                int r = rb + u;
                if (r < n) {
#pragma unroll
                    for (int j = 0; j < 4; j++) {
                        F2U t;
                        t.u = acc[i][j];
                        float v = u ? t.f2.y : t.f2.x;
                        int c = tc * 4 + j;
                        if (res) v += res[(size_t)r * COUT + c];
                        out[(size_t)r * COUT + c] = v;
                    }
                }
            }
        }
    }
}

// cat[i, 0:32] = identity[i,:]; cat[i, 32:64] = x1b[parent[i],:] @ up_W[kid[i]]
__global__ void up_concat(const float* __restrict__ idt, const float* __restrict__ x1,
                          const float* __restrict__ upW,
                          const int* __restrict__ parent, const int* __restrict__ kid,
                          float* __restrict__ cat, int n0) {
    int t = blockIdx.x * blockDim.x + threadIdx.x;
    if (t >= n0 * 64) return;
    int i = t / 64, c = t % 64;
    if (c < 32) {
        cat[t] = idt[(size_t)i * 32 + c];
    } else {
        const float* xr = x1 + (size_t)parent[i] * 64;
        const float* w = upW + (size_t)kid[i] * 64 * 32 + (c - 32);
        float a = 0.f;
#pragma unroll
        for (int ci = 0; ci < 64; ++ci) a += xr[ci] * w[ci * 32];
        cat[t] = a;
    }
}

// out[i,c] = h[i,c] + cat[i,:] @ Wsc[:,c]
__global__ void wsc_add(const float* __restrict__ h, const float* __restrict__ cat,
                        const float* __restrict__ Wsc, float* __restrict__ out, int n0) {
    int t = blockIdx.x * blockDim.x + threadIdx.x;
    if (t >= n0 * 32) return;
    int i = t / 32, c = t % 32;
    float a = h[t];
    const float* xr = cat + (size_t)i * 64;
#pragma unroll
    for (int ci = 0; ci < 64; ++ci) a += xr[ci] * Wsc[ci * 32 + c];
    out[t] = a;
}

// ---------------- host-side orchestration ----------------
static inline int ceil_div(int a, int b) { return (a + b - 1) / b; }
static inline int conv_smem(int cin, int cout, int K, int BR) {
    return 8 * cin * (BR / 2 + 1) + 4 * cin * cout + 4 * BR * K + 8 * cin;
}

extern "C" void kernel_launch(void* const* d_in, const int* in_sizes, int n_in,
                              void* d_out, int out_size) {
    const float* feats     = (const float*)d_in[0];
    const float* res0_W    = (const float*)d_in[1];
    const float* res0_bn   = (const float*)d_in[2];
    const float* down_bn   = (const float*)d_in[3];
    const float* down_W    = (const float*)d_in[4];
    const float* res1_W    = (const float*)d_in[5];
    const float* res1_bn   = (const float*)d_in[6];
    const float* up_bn     = (const float*)d_in[7];
    const float* up_W      = (const float*)d_in[8];
    const float* tail0_bn1 = (const float*)d_in[9];
    const float* tail0_W1  = (const float*)d_in[10];
    const float* tail0_bn2 = (const float*)d_in[11];
    const float* tail0_W2  = (const float*)d_in[12];
    const float* tail0_Wsc = (const float*)d_in[13];
    const float* tail1_W   = (const float*)d_in[14];
    const float* tail1_bn  = (const float*)d_in[15];
    const int* subm0_in    = (const int*)d_in[16];
    const int* subm0_out   = (const int*)d_in[17];
    const int* subm1_in    = (const int*)d_in[18];
    const int* subm1_out   = (const int*)d_in[19];
    const int* down_in     = (const int*)d_in[20];
    const int* down_out    = (const int*)d_in[21];
    const int* n1p         = (const int*)d_in[22];

    const int n0 = in_sizes[0] / 32;
    const int P0 = in_sizes[16] / 27;
    const int P1 = in_sizes[18] / 27;
    const int PD = in_sizes[20] / 8;

    float *f0a, *f0b, *f0c, *cat, *f1a, *f1b, *f1c;
    int *nbr0, *nbr1, *nbrD, *parent, *kid;
    cudaGetSymbolAddress((void**)&f0a, g_f0a);
    cudaGetSymbolAddress((void**)&f0b, g_f0b);
    cudaGetSymbolAddress((void**)&f0c, g_f0c);
    cudaGetSymbolAddress((void**)&cat, g_cat);
    cudaGetSymbolAddress((void**)&f1a, g_f1a);
    cudaGetSymbolAddress((void**)&f1b, g_f1b);
    cudaGetSymbolAddress((void**)&f1c, g_f1c);
    cudaGetSymbolAddress((void**)&nbr0, g_nbr0);
    cudaGetSymbolAddress((void**)&nbr1, g_nbr1);
    cudaGetSymbolAddress((void**)&nbrD, g_nbrD);
    cudaGetSymbolAddress((void**)&parent, g_parent);
    cudaGetSymbolAddress((void**)&kid, g_kid);

    const int S3232 = conv_smem(32, 32, 27, 128);
    const int S3264 = conv_smem(32, 64, 8, 128);
    const int S6464 = conv_smem(64, 64, 27, 64);
    const int S6432 = conv_smem(64, 32, 27, 128);
    cudaFuncSetAttribute(conv_gather<32, 32, 128>, cudaFuncAttributeMaxDynamicSharedMemorySize, S3232);
    cudaFuncSetAttribute(conv_gather<32, 64, 128>, cudaFuncAttributeMaxDynamicSharedMemorySize, S3264);
    cudaFuncSetAttribute(conv_gather<64, 64, 64>,  cudaFuncAttributeMaxDynamicSharedMemorySize, S6464);
    cudaFuncSetAttribute(conv_gather<64, 32, 128>, cudaFuncAttributeMaxDynamicSharedMemorySize, S6432);

    const int TB = 256;
    const int G0_128 = ceil_div(n0, 128);       // 375
    const int G1_128 = ceil_div(N1MAX, 128);    // 250 (early exit on n1)
    const int G1_64  = ceil_div(N1MAX, 64);     // 500 (early exit on n1)
    const int E164 = (N1MAX + 1) * 64;

    // ---- level-0 rulebook, then res0 convs (launch #6 = conv for ncu -s 5) ----
    fill_i32<<<ceil_div((N0 + 1) * 27, TB), TB>>>(nbr0, (N0 + 1) * 27, n0, nullptr);          // 1
    scatter_pairs<<<ceil_div(27 * P0, TB), TB>>>(subm0_in, subm0_out, 27 * P0, P0, 27, nbr0);  // 2

    const float* x = feats;
    for (int rep = 0; rep < 2; ++rep) {                                                        // 3-6
        conv_gather<32, 32, 128><<<G0_128, 128, S3232>>>(
            x, res0_bn + (rep * 2 + 0) * 128, res0_W + (size_t)(rep * 2 + 0) * 27 * 1024,
            nbr0, 27, nullptr, f0c, n0, nullptr, n0, nullptr);
        conv_gather<32, 32, 128><<<G0_128, 128, S3232>>>(
            f0c, res0_bn + (rep * 2 + 1) * 128, res0_W + (size_t)(rep * 2 + 1) * 27 * 1024,
            nbr0, 27, x, f0a, n0, nullptr, n0, nullptr);
        x = f0a;
    }
    // f0a = identity

    // ---- remaining rulebooks ----
    fill_i32<<<ceil_div((N1MAX + 1) * 27, TB), TB>>>(nbr1, (N1MAX + 1) * 27, 0, n1p);
    scatter_pairs<<<ceil_div(27 * P1, TB), TB>>>(subm1_in, subm1_out, 27 * P1, P1, 27, nbr1);
    fill_i32<<<ceil_div((N1MAX + 1) * 8, TB), TB>>>(nbrD, (N1MAX + 1) * 8, n0, nullptr);
    scatter_pairs<<<ceil_div(8 * PD, TB), TB>>>(down_in, down_out, 8 * PD, PD, 8, nbrD);
    fill_i32<<<ceil_div(N0 + 1, TB), TB>>>(parent, N0 + 1, 0, n1p);
    fill_i32<<<ceil_div(N0 + 1, TB), TB>>>(kid, N0 + 1, 0, nullptr);
    scatter_parent<<<ceil_div(8 * PD, TB), TB>>>(down_in, down_out, 8 * PD, PD, n0, parent, kid);

    // ---- down conv (n_out = n1 dev, n_in = n0) ----
    conv_gather<32, 64, 128><<<G1_128, 256, S3264>>>(f0a, down_bn, down_W, nbrD, 8,
                                                     nullptr, f1a, 0, n1p, n0, nullptr);

    // ---- res1 blocks (level 1, C=64) ----
    for (int rep = 0; rep < 2; ++rep) {
        conv_gather<64, 64, 64><<<G1_64, 128, S6464>>>(
            f1a, res1_bn + (rep * 2 + 0) * 256, res1_W + (size_t)(rep * 2 + 0) * 27 * 4096,
            nbr1, 27, nullptr, f1c, 0, n1p, 0, n1p);
        conv_gather<64, 64, 64><<<G1_64, 128, S6464>>>(
            f1c, res1_bn + (rep * 2 + 1) * 256, res1_W + (size_t)(rep * 2 + 1) * 27 * 4096,
            nbr1, 27, f1a, f1a, 0, n1p, 0, n1p);
    }

    // ---- up conv + concat ----
    bnrelu_k<64><<<ceil_div(E164, TB), TB>>>(f1a, up_bn, f1b, 0, n1p, E164);
    up_concat<<<ceil_div(n0 * 64, TB), TB>>>(f0a, f1b, up_W, parent, kid, cat, n0);

    // ---- tail0 ----
    conv_gather<64, 32, 128><<<G0_128, 128, S6432>>>(cat, tail0_bn1, tail0_W1, nbr0, 27,
                                                     nullptr, f0b, n0, nullptr, n0, nullptr);
    conv_gather<32, 32, 128><<<G0_128, 128, S3232>>>(f0b, tail0_bn2, tail0_W2, nbr0, 27,
                                                     nullptr, f0c, n0, nullptr, n0, nullptr);
    wsc_add<<<ceil_div(n0 * 32, TB), TB>>>(f0c, cat, tail0_Wsc, f0b, n0);

    // ---- tail1 res block -> d_out ----
    conv_gather<32, 32, 128><<<G0_128, 128, S3232>>>(f0b, tail1_bn + 0, tail1_W, nbr0, 27,
                                                     nullptr, f0a, n0, nullptr, n0, nullptr);
    conv_gather<32, 32, 128><<<G0_128, 128, S3232>>>(f0a, tail1_bn + 128, tail1_W + 27 * 1024,
                                                     nbr0, 27, f0b, (float*)d_out,
                                                     n0, nullptr, n0, nullptr);
}

// round 6
// speedup vs baseline: 2.5595x; 1.1316x over previous
#include <cuda_runtime.h>

#define N0 48000
#define N1MAX 32000
#define EPSV 1e-4f

// ---------------- scratch (device globals; no allocation) ----------------
__device__ float g_f0a[(N0 + 1) * 32];
__device__ float g_f0b[(N0 + 1) * 32];
__device__ float g_f0c[(N0 + 1) * 32];
__device__ float g_cat[(N0 + 1) * 64];
__device__ float g_f1a[(N1MAX + 1) * 64];
__device__ float g_f1b[(N1MAX + 1) * 64];
__device__ float g_f1c[(N1MAX + 1) * 64];
__device__ int g_nbr0[(N0 + 1) * 27];
__device__ int g_nbr1[(N1MAX + 1) * 27];
__device__ int g_nbrD[(N1MAX + 1) * 8];
__device__ int g_parent[N0 + 1];
__device__ int g_kid[N0 + 1];

// ---------------- f32x2 helpers ----------------
union F2U { float2 f2; unsigned long long u; };

__device__ __forceinline__ unsigned long long dup2(float v) {
    unsigned long long r;
    asm("mov.b64 %0, {%1, %1};" : "=l"(r) : "f"(v));
    return r;
}
__device__ __forceinline__ void ffma2(unsigned long long& acc, unsigned long long a,
                                      unsigned long long b) {
    asm("fma.rn.f32x2 %0, %1, %2, %0;" : "+l"(acc) : "l"(a), "l"(b));
}

// ---------------- small utility kernels ----------------
__global__ void fill_i32(int* p, int count, int val, const int* vptr) {
    int t = blockIdx.x * blockDim.x + threadIdx.x;
    if (t >= count) return;
    p[t] = vptr ? *vptr : val;
}

__global__ void scatter_pairs(const int* __restrict__ pin, const int* __restrict__ pout,
                              int total, int P, int K, int* __restrict__ nbr) {
    int t = blockIdx.x * blockDim.x + threadIdx.x;
    if (t >= total) return;
    int k = t / P;
    nbr[pout[t] * K + k] = pin[t];
}

__global__ void scatter_parent(const int* __restrict__ din, const int* __restrict__ dout,
                               int total, int P, int n0,
                               int* __restrict__ parent, int* __restrict__ kid) {
    int t = blockIdx.x * blockDim.x + threadIdx.x;
    if (t >= total) return;
    int k = t / P;
    int i = din[t];
    if (i < n0) { parent[i] = dout[t]; kid[i] = k; }
}

template <int C>
__global__ void bnrelu_k(const float* __restrict__ x, const float* __restrict__ bn,
                         float* __restrict__ y, int n_host, const int* __restrict__ n_dev,
                         int total) {
    int t = blockIdx.x * blockDim.x + threadIdx.x;
    if (t >= total) return;
    int n = n_dev ? *n_dev : n_host;
    int r = t / C, c = t % C;
    float v = 0.f;
    if (r < n) {
        float g = bn[c], be = bn[C + c], m = bn[2 * C + c], va = bn[3 * C + c];
        v = fmaxf((x[t] - m) * (g * rsqrtf(va + EPSV)) + be, 0.f);
    }
    y[t] = v;
}

// ---------------- gather implicit-GEMM sparse conv, split-K ----------------
// out[r,:] = sum_k bnrelu(x[nbr[r][k],:]) @ W[k]  (+ res[r,:])
// Block = 2 tap-groups; each group has private Xs/Ws and computes the full
// BRxCOUT tile over its half of the taps (8 rows x 4 cols per thread, f32x2
// packed). Group 1 stages its partial sums in smem; group 0 combines+stores.
template <int CIN, int COUT, int BR>
__global__ void conv_gather(const float* __restrict__ x, const float* __restrict__ bn,
                            const float* __restrict__ W,
                            const int* __restrict__ nbr, int K,
                            const float* __restrict__ res, float* __restrict__ out,
                            int nout_h, const int* __restrict__ nout_d,
                            int nin_h, const int* __restrict__ nin_d) {
    constexpr int NPAIR = BR / 2;
    constexpr int P2 = NPAIR + 1;            // odd float2 pitch
    constexpr int TCOL = COUT / 4;
    constexpr int NTG = (BR / 8) * TCOL;     // threads per group
    constexpr int NT = NTG * 2;
    constexpr int XSF = CIN * P2 * 2;        // floats per group Xs
    extern __shared__ float smem[];
    float* stage = smem;                            // BR*COUT (reuses Xs areas)
    int tid = threadIdx.x;
    int g = tid / NTG, tg = tid % NTG;
    float2* Xs  = (float2*)(smem + g * XSF);        // group-private
    float*  Ws  = smem + 2 * XSF + g * CIN * COUT;  // group-private
    int* idxAll = (int*)(smem + 2 * XSF + 2 * CIN * COUT);   // BR*K shared
    float* sc   = (float*)(idxAll + BR * K);
    float* bi   = sc + CIN;

    int n = nout_d ? *nout_d : nout_h;
    int nin = nin_d ? *nin_d : nin_h;
    int tc = tg % TCOL, tr = tg / TCOL;
    int Kh = (K + 1) / 2;

    if (tid < CIN) {
        float gg = bn[tid], be = bn[CIN + tid], m = bn[2 * CIN + tid], va = bn[3 * CIN + tid];
        float s = gg * rsqrtf(va + EPSV);
        sc[tid] = s;
        bi[tid] = be - m * s;
    }

    for (int tile = blockIdx.x; tile * BR < n; tile += gridDim.x) {
        int row0 = tile * BR;
        __syncthreads();  // prev tile fully done (stage/idxAll free); sc/bi ready
        for (int e = tid; e < BR * K; e += NT)
            idxAll[e] = (row0 + e / K < n) ? nbr[(size_t)row0 * K + e] : nin;

        unsigned long long acc[4][4];
#pragma unroll
        for (int a = 0; a < 4; a++)
#pragma unroll
            for (int j = 0; j < 4; j++) acc[a][j] = 0ull;

        for (int kk = 0; kk < Kh; ++kk) {
            int k = g * Kh + kk;
            bool live = (k < K);
            __syncthreads();  // idxAll ready / prev compute done
            if (live) {
                // gather + bnrelu two rows, store pair-packed transposed
                for (int e = tg; e < NPAIR * (CIN / 4); e += NTG) {
                    int m = e / (CIN / 4), c4 = e % (CIN / 4);
                    int i0 = idxAll[(2 * m + 0) * K + k];
                    int i1 = idxAll[(2 * m + 1) * K + k];
                    float4 v0 = make_float4(0.f, 0.f, 0.f, 0.f);
                    float4 v1 = make_float4(0.f, 0.f, 0.f, 0.f);
                    int c = c4 * 4;
                    if (i0 < nin) {
                        v0 = *reinterpret_cast<const float4*>(x + (size_t)i0 * CIN + c);
                        v0.x = fmaxf(fmaf(v0.x, sc[c + 0], bi[c + 0]), 0.f);
                        v0.y = fmaxf(fmaf(v0.y, sc[c + 1], bi[c + 1]), 0.f);
                        v0.z = fmaxf(fmaf(v0.z, sc[c + 2], bi[c + 2]), 0.f);
                        v0.w = fmaxf(fmaf(v0.w, sc[c + 3], bi[c + 3]), 0.f);
                    }
                    if (i1 < nin) {
                        v1 = *reinterpret_cast<const float4*>(x + (size_t)i1 * CIN + c);
                        v1.x = fmaxf(fmaf(v1.x, sc[c + 0], bi[c + 0]), 0.f);
                        v1.y = fmaxf(fmaf(v1.y, sc[c + 1], bi[c + 1]), 0.f);
                        v1.z = fmaxf(fmaf(v1.z, sc[c + 2], bi[c + 2]), 0.f);
                        v1.w = fmaxf(fmaf(v1.w, sc[c + 3], bi[c + 3]), 0.f);
                    }
                    Xs[(c + 0) * P2 + m] = make_float2(v0.x, v1.x);
                    Xs[(c + 1) * P2 + m] = make_float2(v0.y, v1.y);
                    Xs[(c + 2) * P2 + m] = make_float2(v0.z, v1.z);
                    Xs[(c + 3) * P2 + m] = make_float2(v0.w, v1.w);
                }
                for (int e = tg; e < CIN * COUT / 4; e += NTG)
                    *reinterpret_cast<float4*>(Ws + e * 4) =
                        *reinterpret_cast<const float4*>(W + (size_t)k * CIN * COUT + e * 4);
            }
            __syncthreads();
            if (live) {
#pragma unroll
                for (int ci = 0; ci < CIN; ++ci) {
                    F2U xp[4];
#pragma unroll
                    for (int i = 0; i < 4; i++) xp[i].f2 = Xs[ci * P2 + tr * 4 + i];
                    float4 w = *reinterpret_cast<const float4*>(&Ws[ci * COUT + tc * 4]);
                    unsigned long long w0 = dup2(w.x), w1 = dup2(w.y);
                    unsigned long long w2 = dup2(w.z), w3 = dup2(w.w);
#pragma unroll
                    for (int i = 0; i < 4; i++) {
                        ffma2(acc[i][0], xp[i].u, w0);
                        ffma2(acc[i][1], xp[i].u, w1);
                        ffma2(acc[i][2], xp[i].u, w2);
                        ffma2(acc[i][3], xp[i].u, w3);
                    }
                }
            }
        }
        // combine: group1 -> stage, group0 adds + res + store
        __syncthreads();
        if (g == 1) {
#pragma unroll
            for (int i = 0; i < 4; i++) {
                int rb = (tr * 4 + i) * 2;
#pragma unroll
                for (int j = 0; j < 4; j++) {
                    F2U t;
                    t.u = acc[i][j];
                    stage[(rb + 0) * COUT + tc * 4 + j] = t.f2.x;
                    stage[(rb + 1) * COUT + tc * 4 + j] = t.f2.y;
                }
            }
        }
        __syncthreads();
        if (g == 0) {
#pragma unroll
            for (int i = 0; i < 4; i++) {
                int rb = row0 + (tr * 4 + i) * 2;
#pragma unroll
                for (int u = 0; u < 2; u++) {
                    int r = rb + u;
                    if (r < n) {
#pragma unroll
                        for (int j = 0; j < 4; j++) {
                            F2U t;
                            t.u = acc[i][j];
                            float v = (u ? t.f2.y : t.f2.x) +
                                      stage[((tr * 4 + i) * 2 + u) * COUT + tc * 4 + j];
                            int c = tc * 4 + j;
                            if (res) v += res[(size_t)r * COUT + c];
                            out[(size_t)r * COUT + c] = v;
                        }
                    }
                }
            }
        }
    }
}

// cat[i, 0:32] = identity[i,:]; cat[i, 32:64] = x1b[parent[i],:] @ up_W[kid[i]]
__global__ void up_concat(const float* __restrict__ idt, const float* __restrict__ x1,
                          const float* __restrict__ upW,
                          const int* __restrict__ parent, const int* __restrict__ kid,
                          float* __restrict__ cat, int n0) {
    int t = blockIdx.x * blockDim.x + threadIdx.x;
    if (t >= n0 * 64) return;
    int i = t / 64, c = t % 64;
    if (c < 32) {
        cat[t] = idt[(size_t)i * 32 + c];
    } else {
        const float* xr = x1 + (size_t)parent[i] * 64;
        const float* w = upW + (size_t)kid[i] * 64 * 32 + (c - 32);
        float a = 0.f;
#pragma unroll
        for (int ci = 0; ci < 64; ++ci) a += xr[ci] * w[ci * 32];
        cat[t] = a;
    }
}

// out[i,c] = h[i,c] + cat[i,:] @ Wsc[:,c]
__global__ void wsc_add(const float* __restrict__ h, const float* __restrict__ cat,
                        const float* __restrict__ Wsc, float* __restrict__ out, int n0) {
    int t = blockIdx.x * blockDim.x + threadIdx.x;
    if (t >= n0 * 32) return;
    int i = t / 32, c = t % 32;
    float a = h[t];
    const float* xr = cat + (size_t)i * 64;
#pragma unroll
    for (int ci = 0; ci < 64; ++ci) a += xr[ci] * Wsc[ci * 32 + c];
    out[t] = a;
}

// ---------------- host-side orchestration ----------------
static inline int ceil_div(int a, int b) { return (a + b - 1) / b; }
static inline int conv_smem(int cin, int cout, int K, int BR) {
    // 2*(Xs + Ws) + idxAll + sc/bi
    return 2 * (8 * cin * (BR / 2 + 1) + 4 * cin * cout) + 4 * BR * K + 8 * cin;
}

extern "C" void kernel_launch(void* const* d_in, const int* in_sizes, int n_in,
                              void* d_out, int out_size) {
    const float* feats     = (const float*)d_in[0];
    const float* res0_W    = (const float*)d_in[1];
    const float* res0_bn   = (const float*)d_in[2];
    const float* down_bn   = (const float*)d_in[3];
    const float* down_W    = (const float*)d_in[4];
    const float* res1_W    = (const float*)d_in[5];
    const float* res1_bn   = (const float*)d_in[6];
    const float* up_bn     = (const float*)d_in[7];
    const float* up_W      = (const float*)d_in[8];
    const float* tail0_bn1 = (const float*)d_in[9];
    const float* tail0_W1  = (const float*)d_in[10];
    const float* tail0_bn2 = (const float*)d_in[11];
    const float* tail0_W2  = (const float*)d_in[12];
    const float* tail0_Wsc = (const float*)d_in[13];
    const float* tail1_W   = (const float*)d_in[14];
    const float* tail1_bn  = (const float*)d_in[15];
    const int* subm0_in    = (const int*)d_in[16];
    const int* subm0_out   = (const int*)d_in[17];
    const int* subm1_in    = (const int*)d_in[18];
    const int* subm1_out   = (const int*)d_in[19];
    const int* down_in     = (const int*)d_in[20];
    const int* down_out    = (const int*)d_in[21];
    const int* n1p         = (const int*)d_in[22];

    const int n0 = in_sizes[0] / 32;
    const int P0 = in_sizes[16] / 27;
    const int P1 = in_sizes[18] / 27;
    const int PD = in_sizes[20] / 8;

    float *f0a, *f0b, *f0c, *cat, *f1a, *f1b, *f1c;
    int *nbr0, *nbr1, *nbrD, *parent, *kid;
    cudaGetSymbolAddress((void**)&f0a, g_f0a);
    cudaGetSymbolAddress((void**)&f0b, g_f0b);
    cudaGetSymbolAddress((void**)&f0c, g_f0c);
    cudaGetSymbolAddress((void**)&cat, g_cat);
    cudaGetSymbolAddress((void**)&f1a, g_f1a);
    cudaGetSymbolAddress((void**)&f1b, g_f1b);
    cudaGetSymbolAddress((void**)&f1c, g_f1c);
    cudaGetSymbolAddress((void**)&nbr0, g_nbr0);
    cudaGetSymbolAddress((void**)&nbr1, g_nbr1);
    cudaGetSymbolAddress((void**)&nbrD, g_nbrD);
    cudaGetSymbolAddress((void**)&parent, g_parent);
    cudaGetSymbolAddress((void**)&kid, g_kid);

    const int S3232 = conv_smem(32, 32, 27, 128);
    const int S3264 = conv_smem(32, 64, 8, 128);
    const int S6464 = conv_smem(64, 64, 27, 64);
    const int S6432 = conv_smem(64, 32, 27, 128);
    cudaFuncSetAttribute(conv_gather<32, 32, 128>, cudaFuncAttributeMaxDynamicSharedMemorySize, S3232);
    cudaFuncSetAttribute(conv_gather<32, 64, 128>, cudaFuncAttributeMaxDynamicSharedMemorySize, S3264);
    cudaFuncSetAttribute(conv_gather<64, 64, 64>,  cudaFuncAttributeMaxDynamicSharedMemorySize, S6464);
    cudaFuncSetAttribute(conv_gather<64, 32, 128>, cudaFuncAttributeMaxDynamicSharedMemorySize, S6432);

    const int TB = 256;
    const int G0_128 = ceil_div(n0, 128);       // 375
    const int G1_128 = ceil_div(N1MAX, 128);    // 250 (early exit on n1)
    const int G1_64  = ceil_div(N1MAX, 64);     // 500 (early exit on n1)
    const int E164 = (N1MAX + 1) * 64;

    // ---- level-0 rulebook, then res0 convs (launch #6 = conv for ncu -s 5) ----
    fill_i32<<<ceil_div((N0 + 1) * 27, TB), TB>>>(nbr0, (N0 + 1) * 27, n0, nullptr);          // 1
    scatter_pairs<<<ceil_div(27 * P0, TB), TB>>>(subm0_in, subm0_out, 27 * P0, P0, 27, nbr0);  // 2

    const float* x = feats;
    for (int rep = 0; rep < 2; ++rep) {                                                        // 3-6
        conv_gather<32, 32, 128><<<G0_128, 256, S3232>>>(
            x, res0_bn + (rep * 2 + 0) * 128, res0_W + (size_t)(rep * 2 + 0) * 27 * 1024,
            nbr0, 27, nullptr, f0c, n0, nullptr, n0, nullptr);
        conv_gather<32, 32, 128><<<G0_128, 256, S3232>>>(
            f0c, res0_bn + (rep * 2 + 1) * 128, res0_W + (size_t)(rep * 2 + 1) * 27 * 1024,
            nbr0, 27, x, f0a, n0, nullptr, n0, nullptr);
        x = f0a;
    }
    // f0a = identity

    // ---- remaining rulebooks ----
    fill_i32<<<ceil_div((N1MAX + 1) * 27, TB), TB>>>(nbr1, (N1MAX + 1) * 27, 0, n1p);
    scatter_pairs<<<ceil_div(27 * P1, TB), TB>>>(subm1_in, subm1_out, 27 * P1, P1, 27, nbr1);
    fill_i32<<<ceil_div((N1MAX + 1) * 8, TB), TB>>>(nbrD, (N1MAX + 1) * 8, n0, nullptr);
    scatter_pairs<<<ceil_div(8 * PD, TB), TB>>>(down_in, down_out, 8 * PD, PD, 8, nbrD);
    fill_i32<<<ceil_div(N0 + 1, TB), TB>>>(parent, N0 + 1, 0, n1p);
    fill_i32<<<ceil_div(N0 + 1, TB), TB>>>(kid, N0 + 1, 0, nullptr);
    scatter_parent<<<ceil_div(8 * PD, TB), TB>>>(down_in, down_out, 8 * PD, PD, n0, parent, kid);

    // ---- down conv (n_out = n1 dev, n_in = n0) ----
    conv_gather<32, 64, 128><<<G1_128, 512, S3264>>>(f0a, down_bn, down_W, nbrD, 8,
                                                     nullptr, f1a, 0, n1p, n0, nullptr);

    // ---- res1 blocks (level 1, C=64) ----
    for (int rep = 0; rep < 2; ++rep) {
        conv_gather<64, 64, 64><<<G1_64, 256, S6464>>>(
            f1a, res1_bn + (rep * 2 + 0) * 256, res1_W + (size_t)(rep * 2 + 0) * 27 * 4096,
            nbr1, 27, nullptr, f1c, 0, n1p, 0, n1p);
        conv_gather<64, 64, 64><<<G1_64, 256, S6464>>>(
            f1c, res1_bn + (rep * 2 + 1) * 256, res1_W + (size_t)(rep * 2 + 1) * 27 * 4096,
            nbr1, 27, f1a, f1a, 0, n1p, 0, n1p);
    }

    // ---- up conv + concat ----
    bnrelu_k<64><<<ceil_div(E164, TB), TB>>>(f1a, up_bn, f1b, 0, n1p, E164);
    up_concat<<<ceil_div(n0 * 64, TB), TB>>>(f0a, f1b, up_W, parent, kid, cat, n0);

    // ---- tail0 ----
    conv_gather<64, 32, 128><<<G0_128, 256, S6432>>>(cat, tail0_bn1, tail0_W1, nbr0, 27,
                                                     nullptr, f0b, n0, nullptr, n0, nullptr);
    conv_gather<32, 32, 128><<<G0_128, 256, S3232>>>(f0b, tail0_bn2, tail0_W2, nbr0, 27,
                                                     nullptr, f0c, n0, nullptr, n0, nullptr);
    wsc_add<<<ceil_div(n0 * 32, TB), TB>>>(f0c, cat, tail0_Wsc, f0b, n0);

    // ---- tail1 res block -> d_out ----
    conv_gather<32, 32, 128><<<G0_128, 256, S3232>>>(f0b, tail1_bn + 0, tail1_W, nbr0, 27,
                                                     nullptr, f0a, n0, nullptr, n0, nullptr);
    conv_gather<32, 32, 128><<<G0_128, 256, S3232>>>(f0a, tail1_bn + 128, tail1_W + 27 * 1024,
                                                     nbr0, 27, f0b, (float*)d_out,
                                                     n0, nullptr, n0, nullptr);
}